// round 11
// baseline (speedup 1.0000x reference)
#include <cuda_runtime.h>
#include <cuda_fp16.h>
#include <stdint.h>

#define CIN   16
#define COUT  32
#define KNB   27
#define HMAX  300032
#define TILEM 128
#define NTHR  256

// ---------------- device globals ----------------
__device__ uint4  g_xh4[(size_t)HMAX * 2];   // x rows as f16 [h][16], 32B each (9.6 MB)
__device__ uint4  g_wB[1728];                // packed B frags: [s][pair][lane] 16B chunks
__device__ float  g_sum[COUT], g_sqs[COUT];
__device__ float2 g_ab[COUT];

// ---------------- smem layout (bytes) ----------------
#define SM_B     0                           // 27 * 1024 = 27648
#define SM_STG   27648                       // 8 warps * 4 bufs * 16 rows * 48B = 24576
#define SM_PART  52224                       // 8 * 64 * 4 = 2048
#define SM_TOTAL 54272                       // -> 4 CTAs/SM
#define ROWB     48                          // stage row stride (16B-aligned, conflict-free)

__device__ __forceinline__ uint32_t smem_u32(const void* p) {
    uint32_t a;
    asm("{ .reg .u64 t; cvta.to.shared.u64 t, %1; cvt.u32.u64 %0, t; }" : "=r"(a) : "l"(p));
    return a;
}
__device__ __forceinline__ void cp16(uint32_t dst, const void* src) {
    asm volatile("cp.async.cg.shared.global [%0], [%1], 16;" :: "r"(dst), "l"(src) : "memory");
}
__device__ __forceinline__ void zero16(uint32_t dst) {
    asm volatile("st.shared.v4.b32 [%0], {%1, %1, %1, %1};" :: "r"(dst), "r"(0) : "memory");
}
__device__ __forceinline__ void cp_commit() { asm volatile("cp.async.commit_group;" ::: "memory"); }
template <int N> __device__ __forceinline__ void cp_wait() {
    asm volatile("cp.async.wait_group %0;" :: "n"(N) : "memory");
}
__device__ __forceinline__ void ldsv4(uint32_t* f, uint32_t a) {
    asm volatile("ld.shared.v4.b32 {%0,%1,%2,%3}, [%4];"
                 : "=r"(f[0]), "=r"(f[1]), "=r"(f[2]), "=r"(f[3]) : "r"(a));
}
__device__ __forceinline__ void ldmA(uint32_t& a0, uint32_t& a1, uint32_t& a2, uint32_t& a3, uint32_t addr) {
    asm volatile("ldmatrix.sync.aligned.m8n8.x4.shared.b16 {%0,%1,%2,%3}, [%4];"
                 : "=r"(a0), "=r"(a1), "=r"(a2), "=r"(a3) : "r"(addr));
}
__device__ __forceinline__ void mma16816(float* c, uint32_t a0, uint32_t a1, uint32_t a2, uint32_t a3,
                                         uint32_t b0, uint32_t b1) {
    asm volatile("mma.sync.aligned.m16n8k16.row.col.f32.f16.f16.f32 "
                 "{%0,%1,%2,%3}, {%4,%5,%6,%7}, {%8,%9}, {%0,%1,%2,%3};"
                 : "+f"(c[0]), "+f"(c[1]), "+f"(c[2]), "+f"(c[3])
                 : "r"(a0), "r"(a1), "r"(a2), "r"(a3), "r"(b0), "r"(b1));
}

// ---------------- prep kernels ----------------
__global__ void k_init() {
    int t = threadIdx.x;
    if (t < COUT) { g_sum[t] = 0.f; g_sqs[t] = 0.f; }
}

__global__ void k_xprep(const float* __restrict__ x, int H) {
    int h = blockIdx.x * 256 + threadIdx.x;
    if (h >= HMAX) return;
    __half2 v[8];
    if (h < H) {
#pragma unroll
        for (int i = 0; i < 8; i++)
            v[i] = __floats2half2_rn(x[(size_t)(2 * i) * H + h], x[(size_t)(2 * i + 1) * H + h]);
    } else {
#pragma unroll
        for (int i = 0; i < 8; i++) v[i] = __floats2half2_rn(0.f, 0.f);
    }
    uint4* dst = g_xh4 + (size_t)h * 2;
    dst[0] = *(uint4*)&v[0];
    dst[1] = *(uint4*)&v[4];
}

// Pre-packed B fragments for mma.m16n8k16:
//   word index e: j = e&3, lane = (e>>2)&31, pairblk = (e>>7)&1, s = e>>8
//   nt = pairblk*2 + (j>>1); b01 = j&1 (0 -> b0 frag, 1 -> b1 frag)
//   n  = nt*8 + lane/4;  k0 = s*16 + (lane%4)*2 + b01*8;  halves (k0, k0+1)
//   B[n][kc] = w[n][i=kc%16][k=kc/16]   (kc in [0,432))
__global__ void k_wprep(const float* __restrict__ w) {
    int e = blockIdx.x * 256 + threadIdx.x;   // 27*256 = 6912 words
    if (e >= 6912) return;
    int j = e & 3, lane = (e >> 2) & 31, pb = (e >> 7) & 1, s = e >> 8;
    int q = lane & 3, r4 = lane >> 2;
    int nt = pb * 2 + (j >> 1), b01 = j & 1;
    int n = nt * 8 + r4;
    int k0 = s * 16 + q * 2 + b01 * 8;
    float v0 = w[n * 432 + (k0 & 15) * 27 + (k0 >> 4)];
    int k1 = k0 + 1;
    float v1 = w[n * 432 + (k1 & 15) * 27 + (k1 >> 4)];
    __half2 p = __floats2half2_rn(v0, v1);
    ((uint32_t*)g_wB)[e] = *(uint32_t*)&p;
}

// ---------------- main HMMA kernel ----------------
__global__ void __launch_bounds__(NTHR) k_conv(const int* __restrict__ neigh,
                                               float* __restrict__ out, int H) {
    extern __shared__ char smem[];
    uint32_t sb = smem_u32(smem);
    int tid = threadIdx.x, lane = tid & 31, w = tid >> 5;
    int q = lane & 3, r4 = lane >> 2;

    // prologue: B image via cp.async (neigh read directly from gmem, L1-cached)
    for (int j = tid; j < 1728; j += NTHR)           // 27648 B
        cp16(sb + SM_B + j * 16, g_wB + j);
    cp_commit();
    cp_wait<0>();
    __syncthreads();

    // gather geometry: lane -> (row grow, 16B half ghalf)
    int grow = lane >> 1, ghalf = lane & 1;
    long hbase = (long)blockIdx.x * TILEM;
    int wr = w * 16;
    long grh = hbase + wr + grow;
    bool rowok = grh < (long)H;
    const int* nrow = neigh + (size_t)(rowok ? grh : 0) * KNB;   // 108B contiguous, L1-friendly
    uint32_t stw = sb + SM_STG + w * (4 * 16 * ROWB);
    uint32_t gdst0 = stw + grow * ROWB + (ghalf << 4);
    uint32_t lmaddr = stw + (lane & 15) * ROWB + (lane >> 4) * 16;
    uint32_t bbase = sb + SM_B + lane * 16;

    float c[4][4];
#pragma unroll
    for (int nt = 0; nt < 4; nt++)
#pragma unroll
        for (int j = 0; j < 4; j++) c[nt][j] = 0.f;

    // issue gather for step k into buffer (k mod 4)
    auto issue = [&](int k) {
        uint32_t dst = gdst0 + (k & 3) * (16 * ROWB);
        int idx = rowok ? __ldg(nrow + k) : -1;
        if ((unsigned)idx < (unsigned)H)
            cp16(dst, (const char*)g_xh4 + ((size_t)(unsigned)idx << 5) + (ghalf << 4));
        else
            zero16(dst);
        cp_commit();
    };

    issue(0); issue(1); issue(2);
#pragma unroll 1
    for (int k = 0; k < KNB; k++) {
        if (k + 3 < KNB) issue(k + 3);
        else             cp_commit();          // empty group keeps wait depth constant
        cp_wait<3>();
        __syncwarp();
        uint32_t a0, a1, a2, a3;
        ldmA(a0, a1, a2, a3, lmaddr + (k & 3) * (16 * ROWB));
        uint32_t bk = bbase + (uint32_t)k * 1024;
        uint32_t f[4], g[4];
        ldsv4(f, bk);
        ldsv4(g, bk + 512);
        mma16816(c[0], a0, a1, a2, a3, f[0], f[1]);
        mma16816(c[1], a0, a1, a2, a3, f[2], f[3]);
        mma16816(c[2], a0, a1, a2, a3, g[0], g[1]);
        mma16816(c[3], a0, a1, a2, a3, g[2], g[3]);
    }

    // epilogue: direct gmem stores + BN partials
    float* part = (float*)(smem + SM_PART);
    long h  = hbase + wr + r4;
    long h8 = h + 8;
    bool v0 = h < (long)H, v8 = h8 < (long)H;
#pragma unroll
    for (int nt = 0; nt < 4; nt++) {
        int o0 = nt * 8 + 2 * q;
        if (v0) { out[(size_t)o0 * H + h]       = c[nt][0];
                  out[(size_t)(o0 + 1) * H + h] = c[nt][1]; }
        if (v8) { out[(size_t)o0 * H + h8]       = c[nt][2];
                  out[(size_t)(o0 + 1) * H + h8] = c[nt][3]; }
        float s0 = (v0 ? c[nt][0] : 0.f) + (v8 ? c[nt][2] : 0.f);
        float s1 = (v0 ? c[nt][1] : 0.f) + (v8 ? c[nt][3] : 0.f);
        float q0 = (v0 ? c[nt][0] * c[nt][0] : 0.f) + (v8 ? c[nt][2] * c[nt][2] : 0.f);
        float q1 = (v0 ? c[nt][1] * c[nt][1] : 0.f) + (v8 ? c[nt][3] * c[nt][3] : 0.f);
#pragma unroll
        for (int off = 4; off < 32; off <<= 1) {   // reduce over lanes sharing q
            s0 += __shfl_xor_sync(0xffffffffu, s0, off);
            s1 += __shfl_xor_sync(0xffffffffu, s1, off);
            q0 += __shfl_xor_sync(0xffffffffu, q0, off);
            q1 += __shfl_xor_sync(0xffffffffu, q1, off);
        }
        if (r4 == 0) {
            part[w * 64 + o0]          = s0;
            part[w * 64 + o0 + 1]      = s1;
            part[w * 64 + 32 + o0]     = q0;
            part[w * 64 + 32 + o0 + 1] = q1;
        }
    }
    __syncthreads();
    if (tid < 64) {
        float s = 0.f;
#pragma unroll
        for (int wp = 0; wp < 8; wp++) s += part[wp * 64 + tid];
        if (tid < 32) atomicAdd(&g_sum[tid], s);
        else          atomicAdd(&g_sqs[tid - 32], s);
    }
}

// ---------------- BN finalize + normalize ----------------
__global__ void k_fin(const float* __restrict__ gamma, const float* __restrict__ beta, int H) {
    int o = threadIdx.x;
    if (o >= COUT) return;
    float invH = 1.f / (float)H;
    float mean = g_sum[o] * invH;
    float var  = g_sqs[o] * invH - mean * mean;
    float inv  = rsqrtf(var + 1e-5f);
    float a = gamma[o] * inv;
    g_ab[o] = make_float2(a, beta[o] - mean * a);
}

__global__ void k_norm(float* __restrict__ out, int H) {
    int o = blockIdx.y;
    float2 ab = g_ab[o];
    float* base = out + (size_t)o * H;
    int n4 = H >> 2;
    int i4 = blockIdx.x * blockDim.x + threadIdx.x;
    if (i4 < n4) {
        float4* p = (float4*)base + i4;
        float4 v = *p;
        v.x = v.x * ab.x + ab.y;
        v.y = v.y * ab.x + ab.y;
        v.z = v.z * ab.x + ab.y;
        v.w = v.w * ab.x + ab.y;
        *p = v;
    }
    if (blockIdx.x == 0 && threadIdx.x < (H & 3)) {
        int hh = (n4 << 2) + threadIdx.x;
        base[hh] = base[hh] * ab.x + ab.y;
    }
}

extern "C" void kernel_launch(void* const* d_in, const int* in_sizes, int n_in,
                              void* d_out, int out_size) {
    const float* data_in = (const float*)d_in[0];
    const float* weight  = (const float*)d_in[1];
    const float* gamma   = (const float*)d_in[2];
    const float* beta    = (const float*)d_in[3];
    const int*   neigh   = (const int*)d_in[4];
    int H = in_sizes[0] / CIN;
    float* out = (float*)d_out;
    int ntiles = (H + TILEM - 1) / TILEM;

    cudaFuncSetAttribute(k_conv, cudaFuncAttributeMaxDynamicSharedMemorySize, SM_TOTAL);

    k_init<<<1, 64>>>();
    k_xprep<<<HMAX / 256, 256>>>(data_in, H);
    k_wprep<<<27, 256>>>(weight);
    k_conv<<<ntiles, NTHR, SM_TOTAL>>>(neigh, out, H);
    k_fin<<<1, 32>>>(gamma, beta, H);
    dim3 gn((H / 4 + 255) / 256, 32);
    k_norm<<<gn, 256>>>(out, H);
}

// round 12
// speedup vs baseline: 1.3127x; 1.3127x over previous
#include <cuda_runtime.h>
#include <cuda_fp16.h>
#include <stdint.h>

#define CIN   16
#define COUT  32
#define KNB   27
#define HMAX  300032
#define TILEM 128
#define NTHR  256

// ---------------- device globals ----------------
__device__ uint4  g_xh4[(size_t)HMAX * 2];   // x rows as f16 [h][16], 32B each (9.6 MB)
__device__ uint4  g_wB[1728];                // packed B frags: [s][pair][lane] 16B chunks
__device__ float  g_sum[COUT], g_sqs[COUT];
__device__ float2 g_ab[COUT];

// ---------------- smem layout (bytes) ----------------
#define SM_B     0                           // 27 * 1024 = 27648
#define SM_N     27648                       // neigh tile: 128*27*4 = 13824
#define SM_STG   41472                       // 8 warps * 2 bufs * 16 rows * 48B = 12288
#define SM_PART  53760                       // 8 * 64 * 4 = 2048
#define SM_TOTAL 55808                       // -> 4 CTAs/SM
#define ROWB     48                          // stage row stride (16B-aligned, conflict-free)

__device__ __forceinline__ uint32_t smem_u32(const void* p) {
    uint32_t a;
    asm("{ .reg .u64 t; cvta.to.shared.u64 t, %1; cvt.u32.u64 %0, t; }" : "=r"(a) : "l"(p));
    return a;
}
__device__ __forceinline__ void cp16(uint32_t dst, const void* src) {
    asm volatile("cp.async.cg.shared.global [%0], [%1], 16;" :: "r"(dst), "l"(src) : "memory");
}
__device__ __forceinline__ void zero16(uint32_t dst) {
    asm volatile("st.shared.v4.b32 [%0], {%1, %1, %1, %1};" :: "r"(dst), "r"(0) : "memory");
}
__device__ __forceinline__ void cp_commit() { asm volatile("cp.async.commit_group;" ::: "memory"); }
template <int N> __device__ __forceinline__ void cp_wait() {
    asm volatile("cp.async.wait_group %0;" :: "n"(N) : "memory");
}
__device__ __forceinline__ void ldsv4(uint32_t* f, uint32_t a) {
    asm volatile("ld.shared.v4.b32 {%0,%1,%2,%3}, [%4];"
                 : "=r"(f[0]), "=r"(f[1]), "=r"(f[2]), "=r"(f[3]) : "r"(a));
}
__device__ __forceinline__ void ldmA(uint32_t& a0, uint32_t& a1, uint32_t& a2, uint32_t& a3, uint32_t addr) {
    asm volatile("ldmatrix.sync.aligned.m8n8.x4.shared.b16 {%0,%1,%2,%3}, [%4];"
                 : "=r"(a0), "=r"(a1), "=r"(a2), "=r"(a3) : "r"(addr));
}
__device__ __forceinline__ void mma16816(float* c, uint32_t a0, uint32_t a1, uint32_t a2, uint32_t a3,
                                         uint32_t b0, uint32_t b1) {
    asm volatile("mma.sync.aligned.m16n8k16.row.col.f32.f16.f16.f32 "
                 "{%0,%1,%2,%3}, {%4,%5,%6,%7}, {%8,%9}, {%0,%1,%2,%3};"
                 : "+f"(c[0]), "+f"(c[1]), "+f"(c[2]), "+f"(c[3])
                 : "r"(a0), "r"(a1), "r"(a2), "r"(a3), "r"(b0), "r"(b1));
}

// ---------------- prep kernels ----------------
__global__ void k_init() {
    int t = threadIdx.x;
    if (t < COUT) { g_sum[t] = 0.f; g_sqs[t] = 0.f; }
}

__global__ void k_xprep(const float* __restrict__ x, int H) {
    int h = blockIdx.x * 256 + threadIdx.x;
    if (h >= HMAX) return;
    __half2 v[8];
    if (h < H) {
#pragma unroll
        for (int i = 0; i < 8; i++)
            v[i] = __floats2half2_rn(x[(size_t)(2 * i) * H + h], x[(size_t)(2 * i + 1) * H + h]);
    } else {
#pragma unroll
        for (int i = 0; i < 8; i++) v[i] = __floats2half2_rn(0.f, 0.f);
    }
    uint4* dst = g_xh4 + (size_t)h * 2;
    dst[0] = *(uint4*)&v[0];
    dst[1] = *(uint4*)&v[4];
}

// Pre-packed B fragments for mma.m16n8k16 (verified in R10):
//   word index e: j = e&3, lane = (e>>2)&31, pairblk = (e>>7)&1, s = e>>8
//   nt = pairblk*2 + (j>>1); b01 = j&1; n = nt*8 + lane/4;
//   k0 = s*16 + (lane%4)*2 + b01*8; halves (k0, k0+1); B[n][kc] = w[n][kc%16][kc/16]
__global__ void k_wprep(const float* __restrict__ w) {
    int e = blockIdx.x * 256 + threadIdx.x;   // 27*256 = 6912 words
    if (e >= 6912) return;
    int j = e & 3, lane = (e >> 2) & 31, pb = (e >> 7) & 1, s = e >> 8;
    int q = lane & 3, r4 = lane >> 2;
    int nt = pb * 2 + (j >> 1), b01 = j & 1;
    int n = nt * 8 + r4;
    int k0 = s * 16 + q * 2 + b01 * 8;
    float v0 = w[n * 432 + (k0 & 15) * 27 + (k0 >> 4)];
    int k1 = k0 + 1;
    float v1 = w[n * 432 + (k1 & 15) * 27 + (k1 >> 4)];
    __half2 p = __floats2half2_rn(v0, v1);
    ((uint32_t*)g_wB)[e] = *(uint32_t*)&p;
}

// ---------------- main HMMA kernel ----------------
__global__ void __launch_bounds__(NTHR) k_conv(const int* __restrict__ neigh,
                                               float* __restrict__ out, int H) {
    extern __shared__ char smem[];
    uint32_t sb = smem_u32(smem);
    int tid = threadIdx.x, lane = tid & 31, w = tid >> 5;
    int q = lane & 3, r4 = lane >> 2;

    // prologue: B image + neigh tile via cp.async (R9-style)
    for (int j = tid; j < 1728; j += NTHR)           // 27648 B
        cp16(sb + SM_B + j * 16, g_wB + j);
    {
        size_t nlimit = (size_t)H * KNB * 4;
        size_t nbase  = (size_t)blockIdx.x * (TILEM * KNB * 4);
        const char* src = (const char*)neigh;
        for (int j = tid; j < 864; j += NTHR) {
            size_t off = nbase + (size_t)j * 16;
            uint32_t dst = sb + SM_N + j * 16;
            if (off + 16 <= nlimit) {
                cp16(dst, src + off);
            } else {
#pragma unroll
                for (int c = 0; c < 4; c++) {
                    int vv = (off + c * 4 + 4 <= nlimit) ? *(const int*)(src + off + c * 4) : -1;
                    asm volatile("st.shared.b32 [%0], %1;" :: "r"(dst + c * 4), "r"(vv) : "memory");
                }
            }
        }
    }
    cp_commit();
    cp_wait<0>();
    __syncthreads();

    // gather geometry: lane -> (row grow, 16B half ghalf)
    int grow = lane >> 1, ghalf = lane & 1;
    long hbase = (long)blockIdx.x * TILEM;
    int wr = w * 16;
    long grh = hbase + wr + grow;
    bool rowok = grh < (long)H;
    const int* nsh = (const int*)(smem + SM_N) + (wr + grow) * KNB;
    uint32_t stw = sb + SM_STG + w * (2 * 16 * ROWB);
    uint32_t gdst0 = stw + grow * ROWB + (ghalf << 4);
    uint32_t lmaddr = stw + (lane & 15) * ROWB + (lane >> 4) * 16;
    uint32_t bbase = sb + SM_B + lane * 16;

    float c[4][4];
#pragma unroll
    for (int nt = 0; nt < 4; nt++)
#pragma unroll
        for (int j = 0; j < 4; j++) c[nt][j] = 0.f;

    // issue gather for step k into buffer (k mod 2)
    auto issue = [&](int k) {
        uint32_t dst = gdst0 + (k & 1) * (16 * ROWB);
        int idx = rowok ? nsh[k] : -1;
        if ((unsigned)idx < (unsigned)H)
            cp16(dst, (const char*)g_xh4 + ((size_t)(unsigned)idx << 5) + (ghalf << 4));
        else
            zero16(dst);
        cp_commit();
    };

    issue(0);
#pragma unroll 1
    for (int k = 0; k < KNB; k++) {
        if (k + 1 < KNB) { issue(k + 1); cp_wait<1>(); }
        else             { cp_wait<0>(); }
        __syncwarp();
        uint32_t a0, a1, a2, a3;
        ldmA(a0, a1, a2, a3, lmaddr + (k & 1) * (16 * ROWB));
        uint32_t bk = bbase + (uint32_t)k * 1024;
        uint32_t f[4], g[4];
        ldsv4(f, bk);
        ldsv4(g, bk + 512);
        mma16816(c[0], a0, a1, a2, a3, f[0], f[1]);
        mma16816(c[1], a0, a1, a2, a3, f[2], f[3]);
        mma16816(c[2], a0, a1, a2, a3, g[0], g[1]);
        mma16816(c[3], a0, a1, a2, a3, g[2], g[3]);
        __syncwarp();
    }

    // epilogue: direct gmem stores + BN partials
    float* part = (float*)(smem + SM_PART);
    long h  = hbase + wr + r4;
    long h8 = h + 8;
    bool v0 = h < (long)H, v8 = h8 < (long)H;
#pragma unroll
    for (int nt = 0; nt < 4; nt++) {
        int o0 = nt * 8 + 2 * q;
        if (v0) { out[(size_t)o0 * H + h]       = c[nt][0];
                  out[(size_t)(o0 + 1) * H + h] = c[nt][1]; }
        if (v8) { out[(size_t)o0 * H + h8]       = c[nt][2];
                  out[(size_t)(o0 + 1) * H + h8] = c[nt][3]; }
        float s0 = (v0 ? c[nt][0] : 0.f) + (v8 ? c[nt][2] : 0.f);
        float s1 = (v0 ? c[nt][1] : 0.f) + (v8 ? c[nt][3] : 0.f);
        float q0 = (v0 ? c[nt][0] * c[nt][0] : 0.f) + (v8 ? c[nt][2] * c[nt][2] : 0.f);
        float q1 = (v0 ? c[nt][1] * c[nt][1] : 0.f) + (v8 ? c[nt][3] * c[nt][3] : 0.f);
#pragma unroll
        for (int off = 4; off < 32; off <<= 1) {   // reduce over lanes sharing q
            s0 += __shfl_xor_sync(0xffffffffu, s0, off);
            s1 += __shfl_xor_sync(0xffffffffu, s1, off);
            q0 += __shfl_xor_sync(0xffffffffu, q0, off);
            q1 += __shfl_xor_sync(0xffffffffu, q1, off);
        }
        if (r4 == 0) {
            part[w * 64 + o0]          = s0;
            part[w * 64 + o0 + 1]      = s1;
            part[w * 64 + 32 + o0]     = q0;
            part[w * 64 + 32 + o0 + 1] = q1;
        }
    }
    __syncthreads();
    if (tid < 64) {
        float s = 0.f;
#pragma unroll
        for (int wp = 0; wp < 8; wp++) s += part[wp * 64 + tid];
        if (tid < 32) atomicAdd(&g_sum[tid], s);
        else          atomicAdd(&g_sqs[tid - 32], s);
    }
}

// ---------------- BN finalize + normalize ----------------
__global__ void k_fin(const float* __restrict__ gamma, const float* __restrict__ beta, int H) {
    int o = threadIdx.x;
    if (o >= COUT) return;
    float invH = 1.f / (float)H;
    float mean = g_sum[o] * invH;
    float var  = g_sqs[o] * invH - mean * mean;
    float inv  = rsqrtf(var + 1e-5f);
    float a = gamma[o] * inv;
    g_ab[o] = make_float2(a, beta[o] - mean * a);
}

__global__ void k_norm(float* __restrict__ out, int H) {
    int o = blockIdx.y;
    float2 ab = g_ab[o];
    float* base = out + (size_t)o * H;
    int n4 = H >> 2;
    int i4 = blockIdx.x * blockDim.x + threadIdx.x;
    if (i4 < n4) {
        float4* p = (float4*)base + i4;
        float4 v = *p;
        v.x = v.x * ab.x + ab.y;
        v.y = v.y * ab.x + ab.y;
        v.z = v.z * ab.x + ab.y;
        v.w = v.w * ab.x + ab.y;
        *p = v;
    }
    if (blockIdx.x == 0 && threadIdx.x < (H & 3)) {
        int hh = (n4 << 2) + threadIdx.x;
        base[hh] = base[hh] * ab.x + ab.y;
    }
}

extern "C" void kernel_launch(void* const* d_in, const int* in_sizes, int n_in,
                              void* d_out, int out_size) {
    const float* data_in = (const float*)d_in[0];
    const float* weight  = (const float*)d_in[1];
    const float* gamma   = (const float*)d_in[2];
    const float* beta    = (const float*)d_in[3];
    const int*   neigh   = (const int*)d_in[4];
    int H = in_sizes[0] / CIN;
    float* out = (float*)d_out;
    int ntiles = (H + TILEM - 1) / TILEM;

    cudaFuncSetAttribute(k_conv, cudaFuncAttributeMaxDynamicSharedMemorySize, SM_TOTAL);

    k_init<<<1, 64>>>();
    k_xprep<<<HMAX / 256, 256>>>(data_in, H);
    k_wprep<<<27, 256>>>(weight);
    k_conv<<<ntiles, NTHR, SM_TOTAL>>>(neigh, out, H);
    k_fin<<<1, 32>>>(gamma, beta, H);
    dim3 gn((H / 4 + 255) / 256, 32);
    k_norm<<<gn, 256>>>(out, H);
}

// round 13
// speedup vs baseline: 1.4396x; 1.0967x over previous
#include <cuda_runtime.h>
#include <cuda_fp16.h>
#include <stdint.h>

#define CIN   16
#define COUT  32
#define KNB   27
#define HMAX  300032
#define TILEM 128
#define NTHR  256

// ---------------- device globals ----------------
__device__ uint4  g_xh4[(size_t)HMAX * 2];   // x rows as f16 [h][16], 32B each (9.6 MB)
__device__ uint4  g_wB[1728];                // packed B frags: [s][pair][lane] 16B chunks
__device__ float  g_sum[COUT], g_sqs[COUT];
__device__ float2 g_ab[COUT];

// ---------------- smem layout (bytes) ----------------
#define SM_B     0                           // 27 * 1024 = 27648
#define SM_N     27648                       // neigh tile: 128*27*4 = 13824
#define SM_STG   41472                       // 8 warps * 2 bufs * 16 rows * 64B = 16384
#define SM_TOTAL 57856                       // 4 CTAs/SM (4x57856 = 231424 <= 233472)
// BN partials overlay the stage region after the mainloop (guarded by syncthreads)

__device__ __forceinline__ uint32_t smem_u32(const void* p) {
    uint32_t a;
    asm("{ .reg .u64 t; cvta.to.shared.u64 t, %1; cvt.u32.u64 %0, t; }" : "=r"(a) : "l"(p));
    return a;
}
__device__ __forceinline__ void cp16(uint32_t dst, const void* src) {
    asm volatile("cp.async.cg.shared.global [%0], [%1], 16;" :: "r"(dst), "l"(src) : "memory");
}
__device__ __forceinline__ void zero16(uint32_t dst) {
    asm volatile("st.shared.v4.b32 [%0], {%1, %1, %1, %1};" :: "r"(dst), "r"(0) : "memory");
}
__device__ __forceinline__ void cp_commit() { asm volatile("cp.async.commit_group;" ::: "memory"); }
template <int N> __device__ __forceinline__ void cp_wait() {
    asm volatile("cp.async.wait_group %0;" :: "n"(N) : "memory");
}
__device__ __forceinline__ void ldsv4(uint32_t* f, uint32_t a) {
    asm volatile("ld.shared.v4.b32 {%0,%1,%2,%3}, [%4];"
                 : "=r"(f[0]), "=r"(f[1]), "=r"(f[2]), "=r"(f[3]) : "r"(a));
}
__device__ __forceinline__ void ldmA(uint32_t& a0, uint32_t& a1, uint32_t& a2, uint32_t& a3, uint32_t addr) {
    asm volatile("ldmatrix.sync.aligned.m8n8.x4.shared.b16 {%0,%1,%2,%3}, [%4];"
                 : "=r"(a0), "=r"(a1), "=r"(a2), "=r"(a3) : "r"(addr));
}
__device__ __forceinline__ void mma16816(float* c, uint32_t a0, uint32_t a1, uint32_t a2, uint32_t a3,
                                         uint32_t b0, uint32_t b1) {
    asm volatile("mma.sync.aligned.m16n8k16.row.col.f32.f16.f16.f32 "
                 "{%0,%1,%2,%3}, {%4,%5,%6,%7}, {%8,%9}, {%0,%1,%2,%3};"
                 : "+f"(c[0]), "+f"(c[1]), "+f"(c[2]), "+f"(c[3])
                 : "r"(a0), "r"(a1), "r"(a2), "r"(a3), "r"(b0), "r"(b1));
}

// ---------------- prep kernels ----------------
__global__ void k_xprep(const float* __restrict__ x, int H) {
    int h = blockIdx.x * 256 + threadIdx.x;
    if (h >= HMAX) return;
    __half2 v[8];
    if (h < H) {
#pragma unroll
        for (int i = 0; i < 8; i++)
            v[i] = __floats2half2_rn(x[(size_t)(2 * i) * H + h], x[(size_t)(2 * i + 1) * H + h]);
    } else {
#pragma unroll
        for (int i = 0; i < 8; i++) v[i] = __floats2half2_rn(0.f, 0.f);
    }
    uint4* dst = g_xh4 + (size_t)h * 2;
    dst[0] = *(uint4*)&v[0];
    dst[1] = *(uint4*)&v[4];
}

// Pre-packed B fragments for mma.m16n8k16 (verified R10/R12), + fused BN-sum init
__global__ void k_wprep(const float* __restrict__ w) {
    int e = blockIdx.x * 256 + threadIdx.x;   // 27*256 = 6912 words
    if (blockIdx.x == 0 && threadIdx.x < COUT) { g_sum[threadIdx.x] = 0.f; g_sqs[threadIdx.x] = 0.f; }
    if (e >= 6912) return;
    int j = e & 3, lane = (e >> 2) & 31, pb = (e >> 7) & 1, s = e >> 8;
    int q = lane & 3, r4 = lane >> 2;
    int nt = pb * 2 + (j >> 1), b01 = j & 1;
    int n = nt * 8 + r4;
    int k0 = s * 16 + q * 2 + b01 * 8;
    float v0 = w[n * 432 + (k0 & 15) * 27 + (k0 >> 4)];
    int k1 = k0 + 1;
    float v1 = w[n * 432 + (k1 & 15) * 27 + (k1 >> 4)];
    __half2 p = __floats2half2_rn(v0, v1);
    ((uint32_t*)g_wB)[e] = *(uint32_t*)&p;
}

// ---------------- main HMMA kernel ----------------
// Stage row layout (64B rows, 16 rows/buf): row r holds 4 x 16B chunks.
// Logical chunk c = step*2 + half; physical slot = c ^ ((r>>1)&3)  -> conflict-free
// for both cp.async writes and all ldmatrix phases (8 rows hit 8 distinct quads).
__global__ void __launch_bounds__(NTHR, 4) k_conv(const int* __restrict__ neigh,
                                                  float* __restrict__ out, int H) {
    extern __shared__ char smem[];
    uint32_t sb = smem_u32(smem);
    int tid = threadIdx.x, lane = tid & 31, w = tid >> 5;
    int q = lane & 3, r4 = lane >> 2;

    // prologue: B image + neigh tile via cp.async
    for (int j = tid; j < 1728; j += NTHR)           // 27648 B
        cp16(sb + SM_B + j * 16, g_wB + j);
    {
        size_t nlimit = (size_t)H * KNB * 4;
        size_t nbase  = (size_t)blockIdx.x * (TILEM * KNB * 4);
        const char* src = (const char*)neigh;
        for (int j = tid; j < 864; j += NTHR) {
            size_t off = nbase + (size_t)j * 16;
            uint32_t dst = sb + SM_N + j * 16;
            if (off + 16 <= nlimit) {
                cp16(dst, src + off);
            } else {
#pragma unroll
                for (int c = 0; c < 4; c++) {
                    int vv = (off + c * 4 + 4 <= nlimit) ? *(const int*)(src + off + c * 4) : -1;
                    asm volatile("st.shared.b32 [%0], %1;" :: "r"(dst + c * 4), "r"(vv) : "memory");
                }
            }
        }
    }
    cp_commit();
    cp_wait<0>();
    __syncthreads();

    // gather geometry: lane -> (row grow, 16B half ghalf)
    int grow = lane >> 1, ghalf = lane & 1;
    long hbase = (long)blockIdx.x * TILEM;
    int wr = w * 16;
    long grh = hbase + wr + grow;
    bool rowok = grh < (long)H;
    const int* nsh = (const int*)(smem + SM_N) + (wr + grow) * KNB;
    uint32_t stw = sb + SM_STG + w * 2048;
    // gather dst pieces
    uint32_t gbase  = stw + grow * 64;
    uint32_t gsw    = (uint32_t)((grow >> 1) & 3);
    uint32_t gslot0 = ((uint32_t)ghalf ^ gsw) * 16;          // step 0 of pair
    uint32_t gslot1 = ((uint32_t)(2 | ghalf) ^ gsw) * 16;    // step 1 of pair
    // ldmatrix addresses
    int rl = lane & 15, hb = lane >> 4;
    uint32_t lsw = (uint32_t)((rl >> 1) & 3);
    uint32_t lmb = stw + rl * 64;
    uint32_t lm0 = lmb + (((uint32_t)hb) ^ lsw) * 16;        // step 0 of pair
    uint32_t lm1 = lmb + (((uint32_t)(2 | hb)) ^ lsw) * 16;  // step 1 of pair
    uint32_t bbase = sb + SM_B + lane * 16;

    float c[4][4];
#pragma unroll
    for (int nt = 0; nt < 4; nt++)
#pragma unroll
        for (int j = 0; j < 4; j++) c[nt][j] = 0.f;

    // issue gathers for group g (steps 2g, 2g+1) into buffer g&1
    auto issue_group = [&](int g) {
        uint32_t db = gbase + (uint32_t)(g & 1) * 1024;
        int k0 = 2 * g;
        int idx0 = rowok ? nsh[k0] : -1;
        if ((unsigned)idx0 < (unsigned)H)
            cp16(db + gslot0, (const char*)g_xh4 + ((size_t)(unsigned)idx0 << 5) + (ghalf << 4));
        else
            zero16(db + gslot0);
        if (k0 + 1 < KNB) {
            int idx1 = rowok ? nsh[k0 + 1] : -1;
            if ((unsigned)idx1 < (unsigned)H)
                cp16(db + gslot1, (const char*)g_xh4 + ((size_t)(unsigned)idx1 << 5) + (ghalf << 4));
            else
                zero16(db + gslot1);
        }
        cp_commit();
    };

    auto do_step = [&](uint32_t lmaddr, int k) {
        uint32_t a0, a1, a2, a3;
        ldmA(a0, a1, a2, a3, lmaddr);
        uint32_t bk = bbase + (uint32_t)k * 1024;
        uint32_t f[4], g2[4];
        ldsv4(f, bk);
        ldsv4(g2, bk + 512);
        mma16816(c[0], a0, a1, a2, a3, f[0], f[1]);
        mma16816(c[1], a0, a1, a2, a3, f[2], f[3]);
        mma16816(c[2], a0, a1, a2, a3, g2[0], g2[1]);
        mma16816(c[3], a0, a1, a2, a3, g2[2], g2[3]);
    };

    issue_group(0);
#pragma unroll 1
    for (int g = 0; g < 13; g++) {       // groups 0..12 are full 2-step groups
        issue_group(g + 1);
        cp_wait<1>();
        __syncwarp();
        uint32_t boff = (uint32_t)(g & 1) * 1024;
        do_step(lm0 + boff, 2 * g);
        do_step(lm1 + boff, 2 * g + 1);
    }
    // peeled group 13: single step k=26, buffer 1
    cp_wait<0>();
    __syncwarp();
    do_step(lm0 + 1024, 26);

    // stage region is dead for ALL warps after this barrier -> overlay BN partials
    __syncthreads();
    float* part = (float*)(smem + SM_STG);

    long h  = hbase + wr + r4;
    long h8 = h + 8;
    bool v0 = h < (long)H, v8 = h8 < (long)H;
#pragma unroll
    for (int nt = 0; nt < 4; nt++) {
        int o0 = nt * 8 + 2 * q;
        if (v0) { out[(size_t)o0 * H + h]       = c[nt][0];
                  out[(size_t)(o0 + 1) * H + h] = c[nt][1]; }
        if (v8) { out[(size_t)o0 * H + h8]       = c[nt][2];
                  out[(size_t)(o0 + 1) * H + h8] = c[nt][3]; }
        float s0 = (v0 ? c[nt][0] : 0.f) + (v8 ? c[nt][2] : 0.f);
        float s1 = (v0 ? c[nt][1] : 0.f) + (v8 ? c[nt][3] : 0.f);
        float q0 = (v0 ? c[nt][0] * c[nt][0] : 0.f) + (v8 ? c[nt][2] * c[nt][2] : 0.f);
        float q1 = (v0 ? c[nt][1] * c[nt][1] : 0.f) + (v8 ? c[nt][3] * c[nt][3] : 0.f);
#pragma unroll
        for (int off = 4; off < 32; off <<= 1) {   // reduce over lanes sharing q
            s0 += __shfl_xor_sync(0xffffffffu, s0, off);
            s1 += __shfl_xor_sync(0xffffffffu, s1, off);
            q0 += __shfl_xor_sync(0xffffffffu, q0, off);
            q1 += __shfl_xor_sync(0xffffffffu, q1, off);
        }
        if (r4 == 0) {
            part[w * 64 + o0]          = s0;
            part[w * 64 + o0 + 1]      = s1;
            part[w * 64 + 32 + o0]     = q0;
            part[w * 64 + 32 + o0 + 1] = q1;
        }
    }
    __syncthreads();
    if (tid < 64) {
        float s = 0.f;
#pragma unroll
        for (int wp = 0; wp < 8; wp++) s += part[wp * 64 + tid];
        if (tid < 32) atomicAdd(&g_sum[tid], s);
        else          atomicAdd(&g_sqs[tid - 32], s);
    }
}

// ---------------- BN finalize + normalize ----------------
__global__ void k_fin(const float* __restrict__ gamma, const float* __restrict__ beta, int H) {
    int o = threadIdx.x;
    if (o >= COUT) return;
    float invH = 1.f / (float)H;
    float mean = g_sum[o] * invH;
    float var  = g_sqs[o] * invH - mean * mean;
    float inv  = rsqrtf(var + 1e-5f);
    float a = gamma[o] * inv;
    g_ab[o] = make_float2(a, beta[o] - mean * a);
}

__global__ void k_norm(float* __restrict__ out, int H) {
    int o = blockIdx.y;
    float2 ab = g_ab[o];
    float* base = out + (size_t)o * H;
    int n4 = H >> 2;
    int i4 = blockIdx.x * blockDim.x + threadIdx.x;
    if (i4 < n4) {
        float4* p = (float4*)base + i4;
        float4 v = *p;
        v.x = v.x * ab.x + ab.y;
        v.y = v.y * ab.x + ab.y;
        v.z = v.z * ab.x + ab.y;
        v.w = v.w * ab.x + ab.y;
        *p = v;
    }
    if (blockIdx.x == 0 && threadIdx.x < (H & 3)) {
        int hh = (n4 << 2) + threadIdx.x;
        base[hh] = base[hh] * ab.x + ab.y;
    }
}

extern "C" void kernel_launch(void* const* d_in, const int* in_sizes, int n_in,
                              void* d_out, int out_size) {
    const float* data_in = (const float*)d_in[0];
    const float* weight  = (const float*)d_in[1];
    const float* gamma   = (const float*)d_in[2];
    const float* beta    = (const float*)d_in[3];
    const int*   neigh   = (const int*)d_in[4];
    int H = in_sizes[0] / CIN;
    float* out = (float*)d_out;
    int ntiles = (H + TILEM - 1) / TILEM;

    cudaFuncSetAttribute(k_conv, cudaFuncAttributeMaxDynamicSharedMemorySize, SM_TOTAL);

    k_xprep<<<HMAX / 256, 256>>>(data_in, H);
    k_wprep<<<27, 256>>>(weight);
    k_conv<<<ntiles, NTHR, SM_TOTAL>>>(neigh, out, H);
    k_fin<<<1, 32>>>(gamma, beta, H);
    dim3 gn((H / 4 + 255) / 256, 32);
    k_norm<<<gn, 256>>>(out, H);
}

// round 14
// speedup vs baseline: 1.5339x; 1.0655x over previous
#include <cuda_runtime.h>
#include <cuda_fp16.h>
#include <stdint.h>

#define CIN   16
#define COUT  32
#define KNB   27
#define HMAX  300032
#define TILEM 128
#define NTHR  256
#define XBLKS (HMAX / 256)                   // 1172

// ---------------- device globals ----------------
__device__ uint4  g_xh4[(size_t)HMAX * 2];   // x rows as f16 [h][16], 32B each (9.6 MB)
__device__ uint4  g_wB[1728];                // packed B frags: [s][pair][lane] 16B chunks
__device__ float  g_sum[COUT], g_sqs[COUT];

// ---------------- smem layout (bytes) ----------------
#define SM_B     0                           // 27 * 1024 = 27648
#define SM_N     27648                       // neigh tile: 128*27*4 = 13824
#define SM_STG   41472                       // 8 warps * 2 bufs * 16 rows * 64B = 16384
#define SM_TOTAL 57856                       // 4 CTAs/SM
// BN partials overlay the stage region after the mainloop (guarded by syncthreads)

__device__ __forceinline__ uint32_t smem_u32(const void* p) {
    uint32_t a;
    asm("{ .reg .u64 t; cvta.to.shared.u64 t, %1; cvt.u32.u64 %0, t; }" : "=r"(a) : "l"(p));
    return a;
}
__device__ __forceinline__ void cp16(uint32_t dst, const void* src) {
    asm volatile("cp.async.cg.shared.global [%0], [%1], 16;" :: "r"(dst), "l"(src) : "memory");
}
__device__ __forceinline__ void zero16(uint32_t dst) {
    asm volatile("st.shared.v4.b32 [%0], {%1, %1, %1, %1};" :: "r"(dst), "r"(0) : "memory");
}
__device__ __forceinline__ void cp_commit() { asm volatile("cp.async.commit_group;" ::: "memory"); }
template <int N> __device__ __forceinline__ void cp_wait() {
    asm volatile("cp.async.wait_group %0;" :: "n"(N) : "memory");
}
__device__ __forceinline__ void ldsv4(uint32_t* f, uint32_t a) {
    asm volatile("ld.shared.v4.b32 {%0,%1,%2,%3}, [%4];"
                 : "=r"(f[0]), "=r"(f[1]), "=r"(f[2]), "=r"(f[3]) : "r"(a));
}
__device__ __forceinline__ void ldmA(uint32_t& a0, uint32_t& a1, uint32_t& a2, uint32_t& a3, uint32_t addr) {
    asm volatile("ldmatrix.sync.aligned.m8n8.x4.shared.b16 {%0,%1,%2,%3}, [%4];"
                 : "=r"(a0), "=r"(a1), "=r"(a2), "=r"(a3) : "r"(addr));
}
__device__ __forceinline__ void mma16816(float* c, uint32_t a0, uint32_t a1, uint32_t a2, uint32_t a3,
                                         uint32_t b0, uint32_t b1) {
    asm volatile("mma.sync.aligned.m16n8k16.row.col.f32.f16.f16.f32 "
                 "{%0,%1,%2,%3}, {%4,%5,%6,%7}, {%8,%9}, {%0,%1,%2,%3};"
                 : "+f"(c[0]), "+f"(c[1]), "+f"(c[2]), "+f"(c[3])
                 : "r"(a0), "r"(a1), "r"(a2), "r"(a3), "r"(b0), "r"(b1));
}

// ---------------- fused prep: x->f16 rows, w->packed B frags, BN-sum init ----------------
__global__ void k_prep(const float* __restrict__ x, const float* __restrict__ w, int H) {
    int b = blockIdx.x;
    if (b < XBLKS) {
        int h = b * 256 + threadIdx.x;
        if (h >= HMAX) return;
        __half2 v[8];
        if (h < H) {
#pragma unroll
            for (int i = 0; i < 8; i++)
                v[i] = __floats2half2_rn(x[(size_t)(2 * i) * H + h], x[(size_t)(2 * i + 1) * H + h]);
        } else {
#pragma unroll
            for (int i = 0; i < 8; i++) v[i] = __floats2half2_rn(0.f, 0.f);
        }
        uint4* dst = g_xh4 + (size_t)h * 2;
        dst[0] = *(uint4*)&v[0];
        dst[1] = *(uint4*)&v[4];
    } else {
        // weight packing blocks (27 of them); first one also inits BN sums
        int wb = b - XBLKS;
        if (wb == 0 && threadIdx.x < COUT) { g_sum[threadIdx.x] = 0.f; g_sqs[threadIdx.x] = 0.f; }
        int e = wb * 256 + threadIdx.x;          // 27*256 = 6912 words
        if (e >= 6912) return;
        int j = e & 3, lane = (e >> 2) & 31, pb = (e >> 7) & 1, s = e >> 8;
        int q = lane & 3, r4 = lane >> 2;
        int nt = pb * 2 + (j >> 1), b01 = j & 1;
        int n = nt * 8 + r4;
        int k0 = s * 16 + q * 2 + b01 * 8;
        float v0 = w[n * 432 + (k0 & 15) * 27 + (k0 >> 4)];
        int k1 = k0 + 1;
        float v1 = w[n * 432 + (k1 & 15) * 27 + (k1 >> 4)];
        __half2 p = __floats2half2_rn(v0, v1);
        ((uint32_t*)g_wB)[e] = *(uint32_t*)&p;
    }
}

// ---------------- main HMMA kernel (unchanged from R13) ----------------
__global__ void __launch_bounds__(NTHR, 4) k_conv(const int* __restrict__ neigh,
                                                  float* __restrict__ out, int H) {
    extern __shared__ char smem[];
    uint32_t sb = smem_u32(smem);
    int tid = threadIdx.x, lane = tid & 31, w = tid >> 5;
    int q = lane & 3, r4 = lane >> 2;

    // prologue: B image + neigh tile via cp.async
    for (int j = tid; j < 1728; j += NTHR)           // 27648 B
        cp16(sb + SM_B + j * 16, g_wB + j);
    {
        size_t nlimit = (size_t)H * KNB * 4;
        size_t nbase  = (size_t)blockIdx.x * (TILEM * KNB * 4);
        const char* src = (const char*)neigh;
        for (int j = tid; j < 864; j += NTHR) {
            size_t off = nbase + (size_t)j * 16;
            uint32_t dst = sb + SM_N + j * 16;
            if (off + 16 <= nlimit) {
                cp16(dst, src + off);
            } else {
#pragma unroll
                for (int c = 0; c < 4; c++) {
                    int vv = (off + c * 4 + 4 <= nlimit) ? *(const int*)(src + off + c * 4) : -1;
                    asm volatile("st.shared.b32 [%0], %1;" :: "r"(dst + c * 4), "r"(vv) : "memory");
                }
            }
        }
    }
    cp_commit();
    cp_wait<0>();
    __syncthreads();

    // gather geometry: lane -> (row grow, 16B half ghalf)
    int grow = lane >> 1, ghalf = lane & 1;
    long hbase = (long)blockIdx.x * TILEM;
    int wr = w * 16;
    long grh = hbase + wr + grow;
    bool rowok = grh < (long)H;
    const int* nsh = (const int*)(smem + SM_N) + (wr + grow) * KNB;
    uint32_t stw = sb + SM_STG + w * 2048;
    uint32_t gbase  = stw + grow * 64;
    uint32_t gsw    = (uint32_t)((grow >> 1) & 3);
    uint32_t gslot0 = ((uint32_t)ghalf ^ gsw) * 16;
    uint32_t gslot1 = ((uint32_t)(2 | ghalf) ^ gsw) * 16;
    int rl = lane & 15, hb = lane >> 4;
    uint32_t lsw = (uint32_t)((rl >> 1) & 3);
    uint32_t lmb = stw + rl * 64;
    uint32_t lm0 = lmb + (((uint32_t)hb) ^ lsw) * 16;
    uint32_t lm1 = lmb + (((uint32_t)(2 | hb)) ^ lsw) * 16;
    uint32_t bbase = sb + SM_B + lane * 16;

    float c[4][4];
#pragma unroll
    for (int nt = 0; nt < 4; nt++)
#pragma unroll
        for (int j = 0; j < 4; j++) c[nt][j] = 0.f;

    auto issue_group = [&](int g) {
        uint32_t db = gbase + (uint32_t)(g & 1) * 1024;
        int k0 = 2 * g;
        int idx0 = rowok ? nsh[k0] : -1;
        if ((unsigned)idx0 < (unsigned)H)
            cp16(db + gslot0, (const char*)g_xh4 + ((size_t)(unsigned)idx0 << 5) + (ghalf << 4));
        else
            zero16(db + gslot0);
        if (k0 + 1 < KNB) {
            int idx1 = rowok ? nsh[k0 + 1] : -1;
            if ((unsigned)idx1 < (unsigned)H)
                cp16(db + gslot1, (const char*)g_xh4 + ((size_t)(unsigned)idx1 << 5) + (ghalf << 4));
            else
                zero16(db + gslot1);
        }
        cp_commit();
    };

    auto do_step = [&](uint32_t lmaddr, int k) {
        uint32_t a0, a1, a2, a3;
        ldmA(a0, a1, a2, a3, lmaddr);
        uint32_t bk = bbase + (uint32_t)k * 1024;
        uint32_t f[4], g2[4];
        ldsv4(f, bk);
        ldsv4(g2, bk + 512);
        mma16816(c[0], a0, a1, a2, a3, f[0], f[1]);
        mma16816(c[1], a0, a1, a2, a3, f[2], f[3]);
        mma16816(c[2], a0, a1, a2, a3, g2[0], g2[1]);
        mma16816(c[3], a0, a1, a2, a3, g2[2], g2[3]);
    };

    issue_group(0);
#pragma unroll 1
    for (int g = 0; g < 13; g++) {
        issue_group(g + 1);
        cp_wait<1>();
        __syncwarp();
        uint32_t boff = (uint32_t)(g & 1) * 1024;
        do_step(lm0 + boff, 2 * g);
        do_step(lm1 + boff, 2 * g + 1);
    }
    cp_wait<0>();
    __syncwarp();
    do_step(lm0 + 1024, 26);

    __syncthreads();
    float* part = (float*)(smem + SM_STG);

    long h  = hbase + wr + r4;
    long h8 = h + 8;
    bool v0 = h < (long)H, v8 = h8 < (long)H;
#pragma unroll
    for (int nt = 0; nt < 4; nt++) {
        int o0 = nt * 8 + 2 * q;
        if (v0) { out[(size_t)o0 * H + h]       = c[nt][0];
                  out[(size_t)(o0 + 1) * H + h] = c[nt][1]; }
        if (v8) { out[(size_t)o0 * H + h8]       = c[nt][2];
                  out[(size_t)(o0 + 1) * H + h8] = c[nt][3]; }
        float s0 = (v0 ? c[nt][0] : 0.f) + (v8 ? c[nt][2] : 0.f);
        float s1 = (v0 ? c[nt][1] : 0.f) + (v8 ? c[nt][3] : 0.f);
        float q0 = (v0 ? c[nt][0] * c[nt][0] : 0.f) + (v8 ? c[nt][2] * c[nt][2] : 0.f);
        float q1 = (v0 ? c[nt][1] * c[nt][1] : 0.f) + (v8 ? c[nt][3] * c[nt][3] : 0.f);
#pragma unroll
        for (int off = 4; off < 32; off <<= 1) {
            s0 += __shfl_xor_sync(0xffffffffu, s0, off);
            s1 += __shfl_xor_sync(0xffffffffu, s1, off);
            q0 += __shfl_xor_sync(0xffffffffu, q0, off);
            q1 += __shfl_xor_sync(0xffffffffu, q1, off);
        }
        if (r4 == 0) {
            part[w * 64 + o0]          = s0;
            part[w * 64 + o0 + 1]      = s1;
            part[w * 64 + 32 + o0]     = q0;
            part[w * 64 + 32 + o0 + 1] = q1;
        }
    }
    __syncthreads();
    if (tid < 64) {
        float s = 0.f;
#pragma unroll
        for (int wp = 0; wp < 8; wp++) s += part[wp * 64 + tid];
        if (tid < 32) atomicAdd(&g_sum[tid], s);
        else          atomicAdd(&g_sqs[tid - 32], s);
    }
}

// ---------------- normalize (BN finalize folded in) ----------------
__global__ void k_norm(const float* __restrict__ gamma, const float* __restrict__ beta,
                       float* __restrict__ out, int H) {
    int o = blockIdx.y;
    float invH = 1.f / (float)H;
    float mean = g_sum[o] * invH;
    float var  = g_sqs[o] * invH - mean * mean;
    float inv  = rsqrtf(var + 1e-5f);
    float a  = __ldg(gamma + o) * inv;
    float bb = __ldg(beta + o) - mean * a;
    float* base = out + (size_t)o * H;
    int n4 = H >> 2;
    int i4 = blockIdx.x * blockDim.x + threadIdx.x;
    if (i4 < n4) {
        float4* p = (float4*)base + i4;
        float4 v = *p;
        v.x = v.x * a + bb;
        v.y = v.y * a + bb;
        v.z = v.z * a + bb;
        v.w = v.w * a + bb;
        *p = v;
    }
    if (blockIdx.x == 0 && threadIdx.x < (H & 3)) {
        int hh = (n4 << 2) + threadIdx.x;
        base[hh] = base[hh] * a + bb;
    }
}

extern "C" void kernel_launch(void* const* d_in, const int* in_sizes, int n_in,
                              void* d_out, int out_size) {
    const float* data_in = (const float*)d_in[0];
    const float* weight  = (const float*)d_in[1];
    const float* gamma   = (const float*)d_in[2];
    const float* beta    = (const float*)d_in[3];
    const int*   neigh   = (const int*)d_in[4];
    int H = in_sizes[0] / CIN;
    float* out = (float*)d_out;
    int ntiles = (H + TILEM - 1) / TILEM;

    cudaFuncSetAttribute(k_conv, cudaFuncAttributeMaxDynamicSharedMemorySize, SM_TOTAL);

    k_prep<<<XBLKS + 27, 256>>>(data_in, weight, H);
    k_conv<<<ntiles, NTHR, SM_TOTAL>>>(neigh, out, H);
    dim3 gn((H / 4 + 255) / 256, 32);
    k_norm<<<gn, 256>>>(gamma, beta, out, H);
}